// round 6
// baseline (speedup 1.0000x reference)
#include <cuda_runtime.h>
#include <math.h>
#include <stdint.h>

#define BB 128
#define TT 256
#define HH 512
#define G4 2048  // 4*H

// ---------------- scratch (static device memory; no allocations) -------------
__device__ float    g_xproj[134217728];        // 2 dirs * 32768 * 2048 fp32 (512 MB)
__device__ float    g_hist[33554432];          // 2 dirs * 128*256*512 fp32 (128 MB)
__device__ unsigned g_whpack[4u*512u*2048u];   // 4 (l,d) packed tf32 Wh tiles (16 MB)

// ---------------- helpers ----------------------------------------------------
__device__ __forceinline__ unsigned f2tf32(float f) {
    unsigned r;
    asm("cvt.rna.tf32.f32 %0, %1;" : "=r"(r) : "f"(f));
    return r;
}

__device__ __forceinline__ void mma_tf32(float* c, const unsigned* a, const unsigned* b) {
    asm volatile(
        "mma.sync.aligned.m16n8k8.row.col.f32.tf32.tf32.f32 "
        "{%0,%1,%2,%3}, {%4,%5,%6,%7}, {%8,%9}, {%0,%1,%2,%3};"
        : "+f"(c[0]), "+f"(c[1]), "+f"(c[2]), "+f"(c[3])
        : "r"(a[0]), "r"(a[1]), "r"(a[2]), "r"(a[3]),
          "r"(b[0]), "r"(b[1]));
}

__device__ __forceinline__ uint32_t smem_u32(const void* p) {
    uint32_t a;
    asm("{ .reg .u64 t; cvta.to.shared.u64 t, %1; cvt.u32.u64 %0, t; }"
        : "=r"(a) : "l"(p));
    return a;
}

__device__ __forceinline__ uint32_t mapa_u32(uint32_t a, uint32_t rank) {
    uint32_t d;
    asm("mapa.shared::cluster.u32 %0, %1, %2;" : "=r"(d) : "r"(a), "r"(rank));
    return d;
}

__device__ __forceinline__ void st_cluster_u32(uint32_t a, unsigned v) {
    asm volatile("st.shared::cluster.u32 [%0], %1;" :: "r"(a), "r"(v) : "memory");
}

__device__ __forceinline__ void cluster_sync() {
    asm volatile("barrier.cluster.arrive.aligned;" ::: "memory");
    asm volatile("barrier.cluster.wait.aligned;" ::: "memory");
}

// ---------------- Wh pre-pack: fragment-ready tf32 tiles ----------------------
// packed[ld][k8][n8][lane][2]: lane=(g<<2)|tig holds B[k8*8+tig][n8*8+g] and
// B[k8*8+tig+4][n8*8+g] (tf32). Consumer loads a tile's b-fragment as one LDG.64.
__global__ __launch_bounds__(256)
void pack_wh(const float* __restrict__ Wh, unsigned* __restrict__ pk)
{
    const int k8 = blockIdx.x;
    const int ld = blockIdx.z;
    const int w  = threadIdx.x >> 5, lane = threadIdx.x & 31;
    const int n8 = blockIdx.y * 8 + w;
    const int g  = lane >> 2, tig = lane & 3;
    const float* src = Wh + (size_t)ld * 512 * 2048;
    unsigned v0 = f2tf32(src[(size_t)(k8 * 8 + tig)     * 2048 + n8 * 8 + g]);
    unsigned v1 = f2tf32(src[(size_t)(k8 * 8 + tig + 4) * 2048 + n8 * 8 + g]);
    size_t o = ((((size_t)ld * 64 + k8) * 256 + n8) * 64 + lane * 2);
    *(uint2*)(pk + o) = make_uint2(v0, v1);
}

// ---------------- big GEMM: C[M,2048] = A[M,512] @ W[512,2048] + bias --------
// (unchanged known-good kernel)
__global__ __launch_bounds__(256)
void gemm_bias_tf32(const float* __restrict__ A,
                    const float* __restrict__ W,
                    const float* __restrict__ bias,
                    float* __restrict__ C)
{
    __shared__ unsigned As[32][132];
    __shared__ unsigned Bs[32][132];

    const int tid  = threadIdx.x;
    const int w    = tid >> 5;
    const int lane = tid & 31;
    const int g    = lane >> 2;
    const int tig  = lane & 3;
    const int wm   = w >> 2;
    const int wn   = w & 3;
    const long m0  = (long)blockIdx.y * 128;
    const int  n0  = blockIdx.x * 128;

    float acc[4][4][4];
#pragma unroll
    for (int i = 0; i < 4; i++)
#pragma unroll
        for (int j = 0; j < 4; j++)
#pragma unroll
            for (int q = 0; q < 4; q++) acc[i][j][q] = 0.f;

    for (int kk = 0; kk < 512; kk += 32) {
#pragma unroll
        for (int i = 0; i < 4; i++) {
            int lin = tid + i * 256;
            int r = lin >> 3, kq = lin & 7;
            float4 v = *(const float4*)(A + (m0 + r) * 512 + kk + kq * 4);
            As[kq * 4 + 0][r] = f2tf32(v.x);
            As[kq * 4 + 1][r] = f2tf32(v.y);
            As[kq * 4 + 2][r] = f2tf32(v.z);
            As[kq * 4 + 3][r] = f2tf32(v.w);
        }
#pragma unroll
        for (int i = 0; i < 4; i++) {
            int lq = tid + i * 256;
            int k = lq >> 5, cq = lq & 31;
            float4 v = *(const float4*)(W + (size_t)(kk + k) * 2048 + n0 + cq * 4);
            Bs[k][cq * 4 + 0] = f2tf32(v.x);
            Bs[k][cq * 4 + 1] = f2tf32(v.y);
            Bs[k][cq * 4 + 2] = f2tf32(v.z);
            Bs[k][cq * 4 + 3] = f2tf32(v.w);
        }
        __syncthreads();

#pragma unroll
        for (int ks = 0; ks < 4; ks++) {
            const int k0 = ks * 8;
            unsigned a[4][4], bf[4][2];
#pragma unroll
            for (int mt = 0; mt < 4; mt++) {
                int r = wm * 64 + mt * 16;
                a[mt][0] = As[k0 + tig][r + g];
                a[mt][1] = As[k0 + tig][r + g + 8];
                a[mt][2] = As[k0 + tig + 4][r + g];
                a[mt][3] = As[k0 + tig + 4][r + g + 8];
            }
#pragma unroll
            for (int nt = 0; nt < 4; nt++) {
                int cc = wn * 32 + nt * 8 + g;
                bf[nt][0] = Bs[k0 + tig][cc];
                bf[nt][1] = Bs[k0 + tig + 4][cc];
            }
#pragma unroll
            for (int mt = 0; mt < 4; mt++)
#pragma unroll
                for (int nt = 0; nt < 4; nt++)
                    mma_tf32(acc[mt][nt], a[mt], bf[nt]);
        }
        __syncthreads();
    }

#pragma unroll
    for (int mt = 0; mt < 4; mt++) {
#pragma unroll
        for (int nt = 0; nt < 4; nt++) {
            long r0 = m0 + wm * 64 + mt * 16 + g;
            int cc = n0 + wn * 32 + nt * 8 + tig * 2;
            float b0 = bias[cc], b1 = bias[cc + 1];
            C[r0 * 2048 + cc]           = acc[mt][nt][0] + b0;
            C[r0 * 2048 + cc + 1]       = acc[mt][nt][1] + b1;
            C[(r0 + 8) * 2048 + cc]     = acc[mt][nt][2] + b0;
            C[(r0 + 8) * 2048 + cc + 1] = acc[mt][nt][3] + b1;
        }
    }
}

// ---------------- batch-decomposed clustered recurrence ----------------------
// grid (8 j-slices = cluster, 8 batch-groups, 2 dirs), 256 threads.
// CTA: M=16 batches, N=256 gate cols (4 gates x 64 j), K=512.
// h kept in smem A_s[512][24] (tf32); j-slice CTAs exchange h via DSMEM pushes.
struct RecP {
    const float*    xp[2];   // per dir input projections [B*T, 2048]
    const unsigned* pk[2];   // per dir packed Wh
    float*          h[2];    // per dir output base (dir offset folded in)
    long bstride;            // floats per batch
    long tstride;            // floats per timestep
};

#define KRES8     20                       // k8-tiles resident in smem (k < 160)
#define AS_STRIDE 24                       // A_s row stride (conflict-free)
#define AS_WORDS  (512 * AS_STRIDE)        // 12288
#define BRES_WORDS (8 * KRES8 * 4 * 64)    // 40960
#define REC_SMEM  ((AS_WORDS + BRES_WORDS) * 4)   // 212992 B

__global__ __launch_bounds__(256) __cluster_dims__(8, 1, 1)
void lstm_rec(RecP p)
{
    extern __shared__ unsigned sm[];
    unsigned* A_s  = sm;                 // [512][AS_STRIDE] tf32 h, [k][batch]
    unsigned* Bres = sm + AS_WORDS;      // [warp][KRES8][gate][64]

    const int dir = blockIdx.z;
    const int bg  = blockIdx.y;
    const int q   = blockIdx.x;          // cluster rank == j-slice
    const int tid = threadIdx.x;
    const int w   = tid >> 5, lane = tid & 31;
    const int g   = lane >> 2, tig = lane & 3;

    const float*    __restrict__ xp = p.xp[dir];
    const unsigned* __restrict__ pk = p.pk[dir];
    float*          __restrict__ hb = p.h[dir];
    const long bstride = p.bstride, tstride = p.tstride;

    // ---- resident B: warp w's 4 gate tiles for k8 < KRES8 ----
    for (int k8 = 0; k8 < KRES8; k8++) {
#pragma unroll
        for (int gt = 0; gt < 4; gt++) {
            int n8 = gt * 64 + q * 8 + w;
            uint2 v = *(const uint2*)(pk + (((size_t)k8 * 256 + n8) * 64 + lane * 2));
            *(uint2*)(Bres + ((((size_t)w * KRES8 + k8) * 4 + gt) * 64 + lane * 2)) = v;
        }
    }

    // precompute DSMEM target base addresses (step-invariant)
    uint32_t as_local = smem_u32(A_s);
    uint32_t as_remote[8];
#pragma unroll
    for (int r = 0; r < 8; r++) as_remote[r] = mapa_u32(as_local, r);

    float creg[4] = {0.f, 0.f, 0.f, 0.f};

    const int jbase = q * 64 + w * 8 + tig * 2;   // this thread's j, j+1
    const int b0    = bg * 16 + g;                // batches b0, b0+8

    cluster_sync();

    for (int s = 0; s < TT; s++) {
        const int t = dir ? (TT - 1 - s) : s;

        // ---- preload xproj for this (b, t, j) set: hides L2 latency under mma
        float xv[4][4];   // [gate][rr*2+pp]
        {
            const float* x0 = xp + ((size_t)b0 * TT + t) * 2048 + jbase;
            const float* x1 = xp + ((size_t)(b0 + 8) * TT + t) * 2048 + jbase;
#pragma unroll
            for (int gt = 0; gt < 4; gt++) {
                float2 v0 = *(const float2*)(x0 + gt * 512);
                float2 v1 = *(const float2*)(x1 + gt * 512);
                xv[gt][0] = v0.x; xv[gt][1] = v0.y;
                xv[gt][2] = v1.x; xv[gt][3] = v1.y;
            }
        }

        float acc[4][4];
#pragma unroll
        for (int i = 0; i < 4; i++)
#pragma unroll
            for (int j2 = 0; j2 < 4; j2++) acc[i][j2] = 0.f;

        if (s > 0) {
            // resident k8 tiles (smem B)
#pragma unroll 2
            for (int k8 = 0; k8 < KRES8; k8++) {
                unsigned a[4];
                a[0] = A_s[(k8 * 8 + tig) * AS_STRIDE + g];
                a[1] = A_s[(k8 * 8 + tig) * AS_STRIDE + g + 8];
                a[2] = A_s[(k8 * 8 + tig + 4) * AS_STRIDE + g];
                a[3] = A_s[(k8 * 8 + tig + 4) * AS_STRIDE + g + 8];
#pragma unroll
                for (int gt = 0; gt < 4; gt++) {
                    uint2 b2 = *(const uint2*)(Bres +
                        ((((size_t)w * KRES8 + k8) * 4 + gt) * 64 + lane * 2));
                    mma_tf32(acc[gt], a, (const unsigned*)&b2);
                }
            }
            // streamed k8 tiles (L2-resident packed Wh via LDG.64)
#pragma unroll 2
            for (int k8 = KRES8; k8 < 64; k8++) {
                unsigned a[4];
                a[0] = A_s[(k8 * 8 + tig) * AS_STRIDE + g];
                a[1] = A_s[(k8 * 8 + tig) * AS_STRIDE + g + 8];
                a[2] = A_s[(k8 * 8 + tig + 4) * AS_STRIDE + g];
                a[3] = A_s[(k8 * 8 + tig + 4) * AS_STRIDE + g + 8];
#pragma unroll
                for (int gt = 0; gt < 4; gt++) {
                    int n8 = gt * 64 + q * 8 + w;
                    uint2 b2 = *(const uint2*)(pk +
                        (((size_t)k8 * 256 + n8) * 64 + lane * 2));
                    mma_tf32(acc[gt], a, (const unsigned*)&b2);
                }
            }
        }

        // ---- activations + cell update (all 4 gates local to this thread) ----
        float hval[4];
#pragma unroll
        for (int ci = 0; ci < 4; ci++) {
            float gi = acc[0][ci] + xv[0][ci];
            float gf = acc[1][ci] + xv[1][ci];
            float gg = acc[2][ci] + xv[2][ci];
            float go = acc[3][ci] + xv[3][ci];
            float i_ = 1.f / (1.f + expf(-gi));
            float f_ = 1.f / (1.f + expf(-gf));
            float G_ = tanhf(gg);
            float o_ = 1.f / (1.f + expf(-go));
            float cn = f_ * creg[ci] + i_ * G_;
            creg[ci] = cn;
            hval[ci] = o_ * tanhf(cn);
        }

        // global fp32 h write (layer output / next-layer GEMM input)
#pragma unroll
        for (int rr = 0; rr < 2; rr++) {
            int b = b0 + rr * 8;
            *(float2*)(hb + (size_t)b * bstride + (size_t)t * tstride + jbase) =
                make_float2(hval[rr * 2 + 0], hval[rr * 2 + 1]);
        }

        cluster_sync();   // all CTAs finished reading A_s for this step

        // push tf32 h into every cluster member's A_s
        unsigned ht[4];
#pragma unroll
        for (int ci = 0; ci < 4; ci++) ht[ci] = f2tf32(hval[ci]);
#pragma unroll
        for (int r = 0; r < 8; r++) {
#pragma unroll
            for (int rr = 0; rr < 2; rr++) {
#pragma unroll
                for (int pp = 0; pp < 2; pp++) {
                    uint32_t addr = as_remote[r] +
                        (uint32_t)(((jbase + pp) * AS_STRIDE + g + rr * 8) * 4);
                    st_cluster_u32(addr, ht[rr * 2 + pp]);
                }
            }
        }

        cluster_sync();   // exchanged h visible everywhere
    }
}

// ---------------- host orchestration ----------------------------------------
extern "C" void kernel_launch(void* const* d_in, const int* in_sizes, int n_in,
                              void* d_out, int out_size)
{
    const float* x  = (const float*)d_in[0];   // [128,256,512]
    const float* Wx = (const float*)d_in[1];   // [2,2,512,2048]
    const float* Wh = (const float*)d_in[2];   // [2,2,512,2048]
    const float* bs = (const float*)d_in[3];   // [2,2,2048]
    float* out = (float*)d_out;                // [128,256,1024]

    float *xp_base, *hist_base;
    unsigned* pk_base;
    cudaGetSymbolAddress((void**)&xp_base,   g_xproj);
    cudaGetSymbolAddress((void**)&hist_base, g_hist);
    cudaGetSymbolAddress((void**)&pk_base,   g_whpack);

    float* xp[2]   = { xp_base,   xp_base   + (size_t)BB * TT * G4 };
    float* hist[2] = { hist_base, hist_base + (size_t)BB * TT * HH };

    const size_t WSTRIDE = (size_t)HH * G4;    // floats per (l,d) matrix
    const size_t PSTRIDE = (size_t)HH * G4;    // words per packed matrix
    const dim3 ggrid(16, 256);

    cudaFuncSetAttribute(lstm_rec, cudaFuncAttributeMaxDynamicSharedMemorySize,
                         REC_SMEM);

    // ---- pack all 4 Wh matrices into fragment-ready tf32 tiles ----
    pack_wh<<<dim3(64, 32, 4), 256>>>(Wh, pk_base);

    // ---- layer 0 input projections ----
    for (int d = 0; d < 2; d++)
        gemm_bias_tf32<<<ggrid, 256>>>(x, Wx + (size_t)d * WSTRIDE,
                                       bs + d * G4, xp[d]);

    // ---- layer 0 recurrence ----
    {
        RecP p;
        p.xp[0] = xp[0]; p.xp[1] = xp[1];
        p.pk[0] = pk_base + 0 * PSTRIDE;
        p.pk[1] = pk_base + 1 * PSTRIDE;
        p.h[0]  = hist[0]; p.h[1] = hist[1];
        p.bstride = (long)TT * HH;
        p.tstride = HH;
        lstm_rec<<<dim3(8, 8, 2), 256, REC_SMEM>>>(p);
    }

    // ---- layer 1 input projections ----
    for (int d = 0; d < 2; d++)
        gemm_bias_tf32<<<ggrid, 256>>>(hist[d], Wx + (size_t)(2 + d) * WSTRIDE,
                                       bs + (2 + d) * G4, xp[d]);

    // ---- layer 1 recurrence (h written directly into d_out) ----
    {
        RecP p;
        p.xp[0] = xp[0]; p.xp[1] = xp[1];
        p.pk[0] = pk_base + 2 * PSTRIDE;
        p.pk[1] = pk_base + 3 * PSTRIDE;
        p.h[0]  = out; p.h[1] = out + 512;
        p.bstride = (long)TT * 1024;
        p.tstride = 1024;
        lstm_rec<<<dim3(8, 8, 2), 256, REC_SMEM>>>(p);
    }
}

// round 9
// speedup vs baseline: 1.4799x; 1.4799x over previous
#include <cuda_runtime.h>
#include <math.h>
#include <stdint.h>

#define BB 128
#define TT 256
#define HH 512
#define G4 2048  // 4*H

// ---------------- scratch (static device memory; no allocations) -------------
__device__ float g_xproj[134217728];   // 2 dirs * 32768 * 2048 fp32 (512 MB)
__device__ float g_hist[33554432];     // 2 dirs * 128*256*512 fp32 (128 MB)

// grid-barrier state (self-cleaning; relative flag compare)
__device__ unsigned g_barcnt[2];
__device__ unsigned g_barflag[2];

// ---------------- tf32 helpers ----------------------------------------------
__device__ __forceinline__ unsigned f2tf32(float f) {
    unsigned r;
    asm("cvt.rna.tf32.f32 %0, %1;" : "=r"(r) : "f"(f));
    return r;
}

__device__ __forceinline__ void mma_tf32(float* c, const unsigned* a, const unsigned* b) {
    asm volatile(
        "mma.sync.aligned.m16n8k8.row.col.f32.tf32.tf32.f32 "
        "{%0,%1,%2,%3}, {%4,%5,%6,%7}, {%8,%9}, {%0,%1,%2,%3};"
        : "+f"(c[0]), "+f"(c[1]), "+f"(c[2]), "+f"(c[3])
        : "r"(a[0]), "r"(a[1]), "r"(a[2]), "r"(a[3]),
          "r"(b[0]), "r"(b[1]));
}

// ---------------- big GEMM: C[M,2048] = A[M,512] @ W[512,2048] + bias --------
// (known-good R4 kernel, unchanged)
__global__ __launch_bounds__(256)
void gemm_bias_tf32(const float* __restrict__ A,
                    const float* __restrict__ W,
                    const float* __restrict__ bias,
                    float* __restrict__ C)
{
    __shared__ unsigned As[32][132];
    __shared__ unsigned Bs[32][132];

    const int tid  = threadIdx.x;
    const int w    = tid >> 5;
    const int lane = tid & 31;
    const int g    = lane >> 2;
    const int tig  = lane & 3;
    const int wm   = w >> 2;
    const int wn   = w & 3;
    const long m0  = (long)blockIdx.y * 128;
    const int  n0  = blockIdx.x * 128;

    float acc[4][4][4];
#pragma unroll
    for (int i = 0; i < 4; i++)
#pragma unroll
        for (int j = 0; j < 4; j++)
#pragma unroll
            for (int q = 0; q < 4; q++) acc[i][j][q] = 0.f;

    for (int kk = 0; kk < 512; kk += 32) {
#pragma unroll
        for (int i = 0; i < 4; i++) {
            int lin = tid + i * 256;
            int r = lin >> 3, kq = lin & 7;
            float4 v = *(const float4*)(A + (m0 + r) * 512 + kk + kq * 4);
            As[kq * 4 + 0][r] = f2tf32(v.x);
            As[kq * 4 + 1][r] = f2tf32(v.y);
            As[kq * 4 + 2][r] = f2tf32(v.z);
            As[kq * 4 + 3][r] = f2tf32(v.w);
        }
#pragma unroll
        for (int i = 0; i < 4; i++) {
            int lq = tid + i * 256;
            int k = lq >> 5, cq = lq & 31;
            float4 v = *(const float4*)(W + (size_t)(kk + k) * 2048 + n0 + cq * 4);
            Bs[k][cq * 4 + 0] = f2tf32(v.x);
            Bs[k][cq * 4 + 1] = f2tf32(v.y);
            Bs[k][cq * 4 + 2] = f2tf32(v.z);
            Bs[k][cq * 4 + 3] = f2tf32(v.w);
        }
        __syncthreads();

#pragma unroll
        for (int ks = 0; ks < 4; ks++) {
            const int k0 = ks * 8;
            unsigned a[4][4], bf[4][2];
#pragma unroll
            for (int mt = 0; mt < 4; mt++) {
                int r = wm * 64 + mt * 16;
                a[mt][0] = As[k0 + tig][r + g];
                a[mt][1] = As[k0 + tig][r + g + 8];
                a[mt][2] = As[k0 + tig + 4][r + g];
                a[mt][3] = As[k0 + tig + 4][r + g + 8];
            }
#pragma unroll
            for (int nt = 0; nt < 4; nt++) {
                int cc = wn * 32 + nt * 8 + g;
                bf[nt][0] = Bs[k0 + tig][cc];
                bf[nt][1] = Bs[k0 + tig + 4][cc];
            }
#pragma unroll
            for (int mt = 0; mt < 4; mt++)
#pragma unroll
                for (int nt = 0; nt < 4; nt++)
                    mma_tf32(acc[mt][nt], a[mt], bf[nt]);
        }
        __syncthreads();
    }

#pragma unroll
    for (int mt = 0; mt < 4; mt++) {
#pragma unroll
        for (int nt = 0; nt < 4; nt++) {
            long r0 = m0 + wm * 64 + mt * 16 + g;
            int cc = n0 + wn * 32 + nt * 8 + tig * 2;
            float b0 = bias[cc], b1 = bias[cc + 1];
            C[r0 * 2048 + cc]           = acc[mt][nt][0] + b0;
            C[r0 * 2048 + cc + 1]       = acc[mt][nt][1] + b1;
            C[(r0 + 8) * 2048 + cc]     = acc[mt][nt][2] + b0;
            C[(r0 + 8) * 2048 + cc + 1] = acc[mt][nt][3] + b1;
        }
    }
}

// ---------------- persistent recurrence: high-occupancy split-K --------------
// grid (64 j-tiles, 2 dirs), 512 threads = 16 warps (8 M-groups x 2 K-halves).
// CTA tile: M=128 batches, N=32 (4 gates x 8 j), K=512.
// B (Wh) pre-packed in smem as fragment-ready uint2 (1 LDS.64 per mma).
// A (h_prev) fetched straight from global into fragment regs (LDG + cvt),
// depth-1 prefetch. Split-K reduced through padded smem. Per-dir grid barrier.
struct RecP {
    const float* xp[2];   // per dir input projections [B*T, 2048]
    const float* Wh[2];   // per dir [512, 2048]
    float*       h[2];    // per dir h base; (b,t,j) at h + b*bstride + t*tstride + j
    long bstride;
    long tstride;
};

#define BP_WORDS  (64 * 4 * 64)          // 16384: [k8][gate][lane*2]
#define RED_STRIDE 20                    // floats per thread entry (pad: conflict-free)
#define RED_WORDS (8 * 32 * RED_STRIDE)  // 5120
#define REC_SMEM  ((BP_WORDS + RED_WORDS) * 4)   // 86016 B

__global__ __launch_bounds__(512)
void lstm_rec(RecP p)
{
    extern __shared__ unsigned sm[];
    unsigned* Bp = sm;                     // packed Wh fragments
    float* red   = (float*)(sm + BP_WORDS);

    const int dir  = blockIdx.y;
    const int j0   = blockIdx.x * 8;
    const int tid  = threadIdx.x;
    const int wid  = tid >> 5;
    const int lane = tid & 31;
    const int g    = lane >> 2;
    const int tig  = lane & 3;
    const int wm   = wid & 7;      // M-group: rows [wm*16, wm*16+16)
    const int wk   = wid >> 3;     // K-half:  k in [wk*256, wk*256+256)

    const float* __restrict__ xp = p.xp[dir];
    const float* __restrict__ Wh = p.Wh[dir];
    float* __restrict__ hb = p.h[dir];
    const long bstride = p.bstride;
    const long tstride = p.tstride;

    // ---- pack Wh fragments: Bp[(k8*4+gate)*64 + lane*2] = {B[k8*8+tig][col],
    //      B[k8*8+tig+4][col]}, col = gate*512 + j0 + g  (16 warps x 4 k8)
#pragma unroll
    for (int i = 0; i < 4; i++) {
        int k8 = wid * 4 + i;
#pragma unroll
        for (int gt = 0; gt < 4; gt++) {
            size_t col = (size_t)gt * 512 + j0 + g;
            unsigned v0 = f2tf32(Wh[(size_t)(k8 * 8 + tig)     * 2048 + col]);
            unsigned v1 = f2tf32(Wh[(size_t)(k8 * 8 + tig + 4) * 2048 + col]);
            Bp[(k8 * 4 + gt) * 64 + lane * 2]     = v0;
            Bp[(k8 * 4 + gt) * 64 + lane * 2 + 1] = v1;
        }
    }
    __syncthreads();

    float creg[4] = {0.f, 0.f, 0.f, 0.f};
    volatile unsigned* flagp = (volatile unsigned*)&g_barflag[dir];

    const int r0 = wm * 16 + g;        // batch rows r0, r0+8
    const int jj = j0 + tig * 2;       // hidden units jj, jj+1

    for (int s = 0; s < TT; s++) {
        const int t = dir ? (TT - 1 - s) : s;

        // ---- prefetch xproj gates (kgroup0 only; hidden under mma loop) ----
        float xv[4][4];
        if (wk == 0) {
            const float* x0 = xp + ((size_t)r0 * TT + t) * 2048 + jj;
            const float* x1 = xp + ((size_t)(r0 + 8) * TT + t) * 2048 + jj;
#pragma unroll
            for (int gt = 0; gt < 4; gt++) {
                float2 v0 = *(const float2*)(x0 + gt * 512);
                float2 v1 = *(const float2*)(x1 + gt * 512);
                xv[gt][0] = v0.x; xv[gt][1] = v0.y;
                xv[gt][2] = v1.x; xv[gt][3] = v1.y;
            }
        }

        float acc[4][4];
#pragma unroll
        for (int i = 0; i < 4; i++)
#pragma unroll
            for (int q2 = 0; q2 < 4; q2++) acc[i][q2] = 0.f;

        if (s > 0) {
            const int tp = dir ? (t + 1) : (t - 1);
            const float* hp = hb + (size_t)tp * tstride;
            const float* row0 = hp + (size_t)r0 * bstride + wk * 256;
            const float* row1 = hp + (size_t)(r0 + 8) * bstride + wk * 256;

            // depth-1 register prefetch of the A fragment
            float a0n = row0[tig];
            float a1n = row1[tig];
            float a2n = row0[tig + 4];
            float a3n = row1[tig + 4];

#pragma unroll 4
            for (int kk = 0; kk < 32; kk++) {
                unsigned a[4];
                a[0] = f2tf32(a0n); a[1] = f2tf32(a1n);
                a[2] = f2tf32(a2n); a[3] = f2tf32(a3n);
                if (kk < 31) {
                    int kn = (kk + 1) * 8;
                    a0n = row0[kn + tig];
                    a1n = row1[kn + tig];
                    a2n = row0[kn + tig + 4];
                    a3n = row1[kn + tig + 4];
                }
                const int k8g = wk * 32 + kk;
#pragma unroll
                for (int gt = 0; gt < 4; gt++) {
                    uint2 b2 = *(const uint2*)(Bp + (k8g * 4 + gt) * 64 + lane * 2);
                    mma_tf32(acc[gt], a, (const unsigned*)&b2);
                }
            }
        }

        // ---- split-K reduction: kgroup1 -> smem -> kgroup0 ----
        if (wk == 1) {
            float* rp = red + (size_t)(wm * 32 + lane) * RED_STRIDE;
#pragma unroll
            for (int gt = 0; gt < 4; gt++)
                *(float4*)(rp + gt * 4) =
                    make_float4(acc[gt][0], acc[gt][1], acc[gt][2], acc[gt][3]);
        }
        __syncthreads();

        if (wk == 0) {
            const float* rp = red + (size_t)(wm * 32 + lane) * RED_STRIDE;
#pragma unroll
            for (int gt = 0; gt < 4; gt++) {
                float4 v = *(const float4*)(rp + gt * 4);
                acc[gt][0] += v.x; acc[gt][1] += v.y;
                acc[gt][2] += v.z; acc[gt][3] += v.w;
            }

            // ---- activations + cell update; write fp32 h ----
            float hval[4];
#pragma unroll
            for (int q2 = 0; q2 < 4; q2++) {
                float gi = acc[0][q2] + xv[0][q2];
                float gf = acc[1][q2] + xv[1][q2];
                float gg = acc[2][q2] + xv[2][q2];
                float go = acc[3][q2] + xv[3][q2];
                float i_ = 1.f / (1.f + expf(-gi));
                float f_ = 1.f / (1.f + expf(-gf));
                float G_ = tanhf(gg);
                float o_ = 1.f / (1.f + expf(-go));
                float cn = f_ * creg[q2] + i_ * G_;
                creg[q2] = cn;
                hval[q2] = o_ * tanhf(cn);
            }
#pragma unroll
            for (int rr = 0; rr < 2; rr++) {
                int b = r0 + rr * 8;
                *(float2*)(hb + (size_t)b * bstride + (size_t)t * tstride + jj) =
                    make_float2(hval[rr * 2 + 0], hval[rr * 2 + 1]);
            }
        }

        // ---- per-direction grid barrier (64 CTAs), skip after last step ----
        if (s < TT - 1) {
            __threadfence();
            __syncthreads();
            if (tid == 0) {
                unsigned old = *flagp;
                unsigned v = atomicAdd(&g_barcnt[dir], 1);
                if (v == 63) {
                    g_barcnt[dir] = 0;
                    __threadfence();
                    *flagp = old + 1;
                } else {
                    while (*flagp == old) { }
                }
            }
            __syncthreads();
        }
    }
}

// ---------------- host orchestration ----------------------------------------
extern "C" void kernel_launch(void* const* d_in, const int* in_sizes, int n_in,
                              void* d_out, int out_size)
{
    const float* x  = (const float*)d_in[0];   // [128,256,512]
    const float* Wx = (const float*)d_in[1];   // [2,2,512,2048]
    const float* Wh = (const float*)d_in[2];   // [2,2,512,2048]
    const float* bs = (const float*)d_in[3];   // [2,2,2048]
    float* out = (float*)d_out;                // [128,256,1024]

    float *xp_base, *hist_base;
    cudaGetSymbolAddress((void**)&xp_base,   g_xproj);
    cudaGetSymbolAddress((void**)&hist_base, g_hist);

    float* xp[2]   = { xp_base,   xp_base   + (size_t)BB * TT * G4 };
    float* hist[2] = { hist_base, hist_base + (size_t)BB * TT * HH };

    const size_t WSTRIDE = (size_t)HH * G4;
    const dim3 ggrid(16, 256);

    cudaFuncSetAttribute(lstm_rec, cudaFuncAttributeMaxDynamicSharedMemorySize,
                         REC_SMEM);

    // ---- layer 0 input projections ----
    for (int d = 0; d < 2; d++)
        gemm_bias_tf32<<<ggrid, 256>>>(x, Wx + (size_t)d * WSTRIDE,
                                       bs + d * G4, xp[d]);

    // ---- layer 0 recurrence ----
    {
        RecP p;
        p.xp[0] = xp[0]; p.xp[1] = xp[1];
        p.Wh[0] = Wh;    p.Wh[1] = Wh + WSTRIDE;
        p.h[0]  = hist[0]; p.h[1] = hist[1];
        p.bstride = (long)TT * HH;
        p.tstride = HH;
        lstm_rec<<<dim3(64, 2), 512, REC_SMEM>>>(p);
    }

    // ---- layer 1 input projections ----
    for (int d = 0; d < 2; d++)
        gemm_bias_tf32<<<ggrid, 256>>>(hist[d], Wx + (size_t)(2 + d) * WSTRIDE,
                                       bs + (2 + d) * G4, xp[d]);

    // ---- layer 1 recurrence (h lives directly in d_out) ----
    {
        RecP p;
        p.xp[0] = xp[0]; p.xp[1] = xp[1];
        p.Wh[0] = Wh + 2 * WSTRIDE; p.Wh[1] = Wh + 3 * WSTRIDE;
        p.h[0]  = out; p.h[1] = out + 512;
        p.bstride = (long)TT * 1024;
        p.tstride = 1024;
        lstm_rec<<<dim3(64, 2), 512, REC_SMEM>>>(p);
    }
}

// round 10
// speedup vs baseline: 2.4234x; 1.6376x over previous
#include <cuda_runtime.h>
#include <math.h>
#include <stdint.h>

#define BB 128
#define TT 256
#define HH 512
#define G4 2048  // 4*H

// ---------------- scratch (static device memory; no allocations) -------------
__device__ float    g_xproj[134217728];   // 2 dirs * 32768 * 2048 fp32 (512 MB)
__device__ float    g_hist[33554432];     // 2 dirs * 128*256*512 fp32 (128 MB)
__device__ unsigned g_apack[33554432];    // 2 packed A matrices (fragment-major) 128 MB
__device__ unsigned g_bpack[4194304];     // 4 packed Wx matrices (fragment-major) 16 MB

// grid-barrier state (self-cleaning; relative flag compare)
__device__ unsigned g_barcnt[2];
__device__ unsigned g_barflag[2];

// ---------------- tf32 helpers ----------------------------------------------
__device__ __forceinline__ unsigned f2tf32(float f) {
    unsigned r;
    asm("cvt.rna.tf32.f32 %0, %1;" : "=r"(r) : "f"(f));
    return r;
}

__device__ __forceinline__ void mma_tf32(float* c, const unsigned* a, const unsigned* b) {
    asm volatile(
        "mma.sync.aligned.m16n8k8.row.col.f32.tf32.tf32.f32 "
        "{%0,%1,%2,%3}, {%4,%5,%6,%7}, {%8,%9}, {%0,%1,%2,%3};"
        : "+f"(c[0]), "+f"(c[1]), "+f"(c[2]), "+f"(c[3])
        : "r"(a[0]), "r"(a[1]), "r"(a[2]), "r"(a[3]),
          "r"(b[0]), "r"(b[1]));
}

// ---------------- operand pack kernels ---------------------------------------
// A pack: A[M=32768, K=512] fp32 -> Ag[k8][rg][lane][4] tf32 fragment-major.
// entry = {A[rg*16+g][k8*8+tig], A[rg*16+g+8][k8*8+tig],
//          A[rg*16+g][k8*8+tig+4], A[rg*16+g+8][k8*8+tig+4]}
__global__ __launch_bounds__(256)
void pack_a(const float* __restrict__ A, unsigned* __restrict__ Ag)
{
    const int k8  = blockIdx.x;                 // 0..63
    const int rg  = blockIdx.y * 8 + (threadIdx.x >> 5);   // 0..2047
    const int lane = threadIdx.x & 31;
    const int g = lane >> 2, tig = lane & 3;
    const size_t r0 = (size_t)(rg * 16 + g) * 512;
    const size_t r1 = r0 + 8 * 512;
    const int c0 = k8 * 8 + tig;
    uint4 u;
    u.x = f2tf32(A[r0 + c0]);
    u.y = f2tf32(A[r1 + c0]);
    u.z = f2tf32(A[r0 + c0 + 4]);
    u.w = f2tf32(A[r1 + c0 + 4]);
    *(uint4*)(Ag + ((size_t)k8 * 2048 + rg) * 128 + lane * 4) = u;
}

// B pack: Wx[ld][K=512, N=2048] fp32 -> Bg[ld][k8][n8][lane][2] tf32.
// entry = {W[k8*8+tig][n8*8+g], W[k8*8+tig+4][n8*8+g]}
__global__ __launch_bounds__(256)
void pack_b(const float* __restrict__ Wx, unsigned* __restrict__ Bg)
{
    const int k8 = blockIdx.x;                  // 0..63
    const int n8 = blockIdx.y * 8 + (threadIdx.x >> 5);    // 0..255
    const int ld = blockIdx.z;                  // 0..3
    const int lane = threadIdx.x & 31;
    const int g = lane >> 2, tig = lane & 3;
    const float* W = Wx + (size_t)ld * 512 * 2048;
    const size_t col = (size_t)n8 * 8 + g;
    uint2 u;
    u.x = f2tf32(W[(size_t)(k8 * 8 + tig)     * 2048 + col]);
    u.y = f2tf32(W[(size_t)(k8 * 8 + tig + 4) * 2048 + col]);
    *(uint2*)(Bg + (((size_t)ld * 64 + k8) * 256 + n8) * 64 + lane * 2) = u;
}

// ---------------- zero-smem packed-fragment GEMM ------------------------------
// C[M,2048] = A[M,512] @ W[512,2048] + bias, A/B in fragment-major layout.
// CTA 128x128, 8 warps = 2(m) x 4(n), warp tile 64x32. No smem, no syncs.
__global__ __launch_bounds__(256)
void gemm_pk(const unsigned* __restrict__ Ag,
             const unsigned* __restrict__ Bg,
             const float* __restrict__ bias,
             float* __restrict__ C)
{
    const int tid  = threadIdx.x;
    const int wid  = tid >> 5;
    const int lane = tid & 31;
    const int g    = lane >> 2;
    const int tig  = lane & 3;
    const int wm   = wid >> 2;      // 0..1
    const int wn   = wid & 3;       // 0..3
    const long m0  = (long)blockIdx.y * 128;
    const int  n0  = blockIdx.x * 128;
    const int  rgb = blockIdx.y * 8 + wm * 4;    // rowgroup16 base
    const int  n8b = blockIdx.x * 16 + wn * 4;   // colgroup8 base

    const uint4* __restrict__ A4 = (const uint4*)Ag;
    const uint2* __restrict__ B2 = (const uint2*)Bg;

    float acc[4][4][4];
#pragma unroll
    for (int i = 0; i < 4; i++)
#pragma unroll
        for (int j = 0; j < 4; j++)
#pragma unroll
            for (int q = 0; q < 4; q++) acc[i][j][q] = 0.f;

    // prefetch k8 = 0
    uint4 av[4]; uint2 bv[4];
#pragma unroll
    for (int mt = 0; mt < 4; mt++)
        av[mt] = A4[(size_t)(rgb + mt) * 32 + lane];
#pragma unroll
    for (int nt = 0; nt < 4; nt++)
        bv[nt] = B2[(size_t)(n8b + nt) * 32 + lane];

#pragma unroll 4
    for (int k8 = 0; k8 < 64; k8++) {
        uint4 an[4]; uint2 bn[4];
        if (k8 < 63) {
            const size_t ao = (size_t)(k8 + 1) * 65536;   // 2048*32 uint4 per k8
            const size_t bo = (size_t)(k8 + 1) * 8192;    // 256*32 uint2 per k8
#pragma unroll
            for (int mt = 0; mt < 4; mt++)
                an[mt] = A4[ao + (size_t)(rgb + mt) * 32 + lane];
#pragma unroll
            for (int nt = 0; nt < 4; nt++)
                bn[nt] = B2[bo + (size_t)(n8b + nt) * 32 + lane];
        }
#pragma unroll
        for (int mt = 0; mt < 4; mt++)
#pragma unroll
            for (int nt = 0; nt < 4; nt++)
                mma_tf32(acc[mt][nt], (const unsigned*)&av[mt],
                         (const unsigned*)&bv[nt]);
        if (k8 < 63) {
#pragma unroll
            for (int mt = 0; mt < 4; mt++) av[mt] = an[mt];
#pragma unroll
            for (int nt = 0; nt < 4; nt++) bv[nt] = bn[nt];
        }
    }

    // epilogue: + bias, fp32 store
#pragma unroll
    for (int mt = 0; mt < 4; mt++) {
#pragma unroll
        for (int nt = 0; nt < 4; nt++) {
            long r0 = m0 + wm * 64 + mt * 16 + g;
            int cc = n0 + wn * 32 + nt * 8 + tig * 2;
            float b0 = bias[cc], b1 = bias[cc + 1];
            C[r0 * 2048 + cc]           = acc[mt][nt][0] + b0;
            C[r0 * 2048 + cc + 1]       = acc[mt][nt][1] + b1;
            C[(r0 + 8) * 2048 + cc]     = acc[mt][nt][2] + b0;
            C[(r0 + 8) * 2048 + cc + 1] = acc[mt][nt][3] + b1;
        }
    }
}

// ---------------- persistent recurrence (unchanged from R9) ------------------
struct RecP {
    const float* xp[2];
    const float* Wh[2];
    float*       h[2];
    long bstride;
    long tstride;
};

#define BP_WORDS  (64 * 4 * 64)
#define RED_STRIDE 20
#define RED_WORDS (8 * 32 * RED_STRIDE)
#define REC_SMEM  ((BP_WORDS + RED_WORDS) * 4)

__global__ __launch_bounds__(512)
void lstm_rec(RecP p)
{
    extern __shared__ unsigned sm[];
    unsigned* Bp = sm;
    float* red   = (float*)(sm + BP_WORDS);

    const int dir  = blockIdx.y;
    const int j0   = blockIdx.x * 8;
    const int tid  = threadIdx.x;
    const int wid  = tid >> 5;
    const int lane = tid & 31;
    const int g    = lane >> 2;
    const int tig  = lane & 3;
    const int wm   = wid & 7;
    const int wk   = wid >> 3;

    const float* __restrict__ xp = p.xp[dir];
    const float* __restrict__ Wh = p.Wh[dir];
    float* __restrict__ hb = p.h[dir];
    const long bstride = p.bstride;
    const long tstride = p.tstride;

#pragma unroll
    for (int i = 0; i < 4; i++) {
        int k8 = wid * 4 + i;
#pragma unroll
        for (int gt = 0; gt < 4; gt++) {
            size_t col = (size_t)gt * 512 + j0 + g;
            unsigned v0 = f2tf32(Wh[(size_t)(k8 * 8 + tig)     * 2048 + col]);
            unsigned v1 = f2tf32(Wh[(size_t)(k8 * 8 + tig + 4) * 2048 + col]);
            Bp[(k8 * 4 + gt) * 64 + lane * 2]     = v0;
            Bp[(k8 * 4 + gt) * 64 + lane * 2 + 1] = v1;
        }
    }
    __syncthreads();

    float creg[4] = {0.f, 0.f, 0.f, 0.f};
    volatile unsigned* flagp = (volatile unsigned*)&g_barflag[dir];

    const int r0 = wm * 16 + g;
    const int jj = j0 + tig * 2;

    for (int s = 0; s < TT; s++) {
        const int t = dir ? (TT - 1 - s) : s;

        float xv[4][4];
        if (wk == 0) {
            const float* x0 = xp + ((size_t)r0 * TT + t) * 2048 + jj;
            const float* x1 = xp + ((size_t)(r0 + 8) * TT + t) * 2048 + jj;
#pragma unroll
            for (int gt = 0; gt < 4; gt++) {
                float2 v0 = *(const float2*)(x0 + gt * 512);
                float2 v1 = *(const float2*)(x1 + gt * 512);
                xv[gt][0] = v0.x; xv[gt][1] = v0.y;
                xv[gt][2] = v1.x; xv[gt][3] = v1.y;
            }
        }

        float acc[4][4];
#pragma unroll
        for (int i = 0; i < 4; i++)
#pragma unroll
            for (int q2 = 0; q2 < 4; q2++) acc[i][q2] = 0.f;

        if (s > 0) {
            const int tp = dir ? (t + 1) : (t - 1);
            const float* hp = hb + (size_t)tp * tstride;
            const float* row0 = hp + (size_t)r0 * bstride + wk * 256;
            const float* row1 = hp + (size_t)(r0 + 8) * bstride + wk * 256;

            float a0n = row0[tig];
            float a1n = row1[tig];
            float a2n = row0[tig + 4];
            float a3n = row1[tig + 4];

#pragma unroll 4
            for (int kk = 0; kk < 32; kk++) {
                unsigned a[4];
                a[0] = f2tf32(a0n); a[1] = f2tf32(a1n);
                a[2] = f2tf32(a2n); a[3] = f2tf32(a3n);
                if (kk < 31) {
                    int kn = (kk + 1) * 8;
                    a0n = row0[kn + tig];
                    a1n = row1[kn + tig];
                    a2n = row0[kn + tig + 4];
                    a3n = row1[kn + tig + 4];
                }
                const int k8g = wk * 32 + kk;
#pragma unroll
                for (int gt = 0; gt < 4; gt++) {
                    uint2 b2 = *(const uint2*)(Bp + (k8g * 4 + gt) * 64 + lane * 2);
                    mma_tf32(acc[gt], a, (const unsigned*)&b2);
                }
            }
        }

        if (wk == 1) {
            float* rp = red + (size_t)(wm * 32 + lane) * RED_STRIDE;
#pragma unroll
            for (int gt = 0; gt < 4; gt++)
                *(float4*)(rp + gt * 4) =
                    make_float4(acc[gt][0], acc[gt][1], acc[gt][2], acc[gt][3]);
        }
        __syncthreads();

        if (wk == 0) {
            const float* rp = red + (size_t)(wm * 32 + lane) * RED_STRIDE;
#pragma unroll
            for (int gt = 0; gt < 4; gt++) {
                float4 v = *(const float4*)(rp + gt * 4);
                acc[gt][0] += v.x; acc[gt][1] += v.y;
                acc[gt][2] += v.z; acc[gt][3] += v.w;
            }

            float hval[4];
#pragma unroll
            for (int q2 = 0; q2 < 4; q2++) {
                float gi = acc[0][q2] + xv[0][q2];
                float gf = acc[1][q2] + xv[1][q2];
                float gg = acc[2][q2] + xv[2][q2];
                float go = acc[3][q2] + xv[3][q2];
                float i_ = 1.f / (1.f + expf(-gi));
                float f_ = 1.f / (1.f + expf(-gf));
                float G_ = tanhf(gg);
                float o_ = 1.f / (1.f + expf(-go));
                float cn = f_ * creg[q2] + i_ * G_;
                creg[q2] = cn;
                hval[q2] = o_ * tanhf(cn);
            }
#pragma unroll
            for (int rr = 0; rr < 2; rr++) {
                int b = r0 + rr * 8;
                *(float2*)(hb + (size_t)b * bstride + (size_t)t * tstride + jj) =
                    make_float2(hval[rr * 2 + 0], hval[rr * 2 + 1]);
            }
        }

        if (s < TT - 1) {
            __threadfence();
            __syncthreads();
            if (tid == 0) {
                unsigned old = *flagp;
                unsigned v = atomicAdd(&g_barcnt[dir], 1);
                if (v == 63) {
                    g_barcnt[dir] = 0;
                    __threadfence();
                    *flagp = old + 1;
                } else {
                    while (*flagp == old) { }
                }
            }
            __syncthreads();
        }
    }
}

// ---------------- host orchestration ----------------------------------------
extern "C" void kernel_launch(void* const* d_in, const int* in_sizes, int n_in,
                              void* d_out, int out_size)
{
    const float* x  = (const float*)d_in[0];   // [128,256,512]
    const float* Wx = (const float*)d_in[1];   // [2,2,512,2048]
    const float* Wh = (const float*)d_in[2];   // [2,2,512,2048]
    const float* bs = (const float*)d_in[3];   // [2,2,2048]
    float* out = (float*)d_out;                // [128,256,1024]

    float *xp_base, *hist_base;
    unsigned *ap_base, *bp_base;
    cudaGetSymbolAddress((void**)&xp_base,   g_xproj);
    cudaGetSymbolAddress((void**)&hist_base, g_hist);
    cudaGetSymbolAddress((void**)&ap_base,   g_apack);
    cudaGetSymbolAddress((void**)&bp_base,   g_bpack);

    float* xp[2]   = { xp_base,   xp_base   + (size_t)BB * TT * G4 };
    float* hist[2] = { hist_base, hist_base + (size_t)BB * TT * HH };
    unsigned* ap[2] = { ap_base, ap_base + (size_t)64 * 2048 * 128 };

    const size_t WSTRIDE = (size_t)HH * G4;          // floats per (l,d) matrix
    const size_t BPSTRIDE = (size_t)64 * 256 * 64;   // words per packed B

    cudaFuncSetAttribute(lstm_rec, cudaFuncAttributeMaxDynamicSharedMemorySize,
                         REC_SMEM);

    const dim3 ggrid(16, 256);
    const dim3 agrid(64, 256);

    // ---- pack all 4 Wx matrices (one-shot, fragment-major) ----
    pack_b<<<dim3(64, 32, 4), 256>>>(Wx, bp_base);

    // ---- layer 0: pack x, run both direction projections ----
    pack_a<<<agrid, 256>>>(x, ap[0]);
    for (int d = 0; d < 2; d++)
        gemm_pk<<<ggrid, 256>>>(ap[0], bp_base + (size_t)d * BPSTRIDE,
                                bs + d * G4, xp[d]);

    // ---- layer 0 recurrence ----
    {
        RecP p;
        p.xp[0] = xp[0]; p.xp[1] = xp[1];
        p.Wh[0] = Wh;    p.Wh[1] = Wh + WSTRIDE;
        p.h[0]  = hist[0]; p.h[1] = hist[1];
        p.bstride = (long)TT * HH;
        p.tstride = HH;
        lstm_rec<<<dim3(64, 2), 512, REC_SMEM>>>(p);
    }

    // ---- layer 1: pack hidden histories, run projections ----
    pack_a<<<agrid, 256>>>(hist[0], ap[0]);
    pack_a<<<agrid, 256>>>(hist[1], ap[1]);
    for (int d = 0; d < 2; d++)
        gemm_pk<<<ggrid, 256>>>(ap[d], bp_base + (size_t)(2 + d) * BPSTRIDE,
                                bs + (2 + d) * G4, xp[d]);

    // ---- layer 1 recurrence (h lives directly in d_out) ----
    {
        RecP p;
        p.xp[0] = xp[0]; p.xp[1] = xp[1];
        p.Wh[0] = Wh + 2 * WSTRIDE; p.Wh[1] = Wh + 3 * WSTRIDE;
        p.h[0]  = out; p.h[1] = out + 512;
        p.bstride = (long)TT * 1024;
        p.tstride = 1024;
        lstm_rec<<<dim3(64, 2), 512, REC_SMEM>>>(p);
    }
}

// round 11
// speedup vs baseline: 3.2944x; 1.3594x over previous
#include <cuda_runtime.h>
#include <math.h>
#include <stdint.h>

#define BB 128
#define TT 256
#define HH 512
#define G4 2048  // 4*H

// ---------------- scratch (static device memory; no allocations) -------------
__device__ float    g_xproj[134217728];   // 2 dirs * 32768 * 2048 fp32 (512 MB)
__device__ float    g_hist[33554432];     // 2 dirs * 128*256*512 fp32 (128 MB)
__device__ unsigned g_apack[33554432];    // 2 packed A matrices (fragment-major) 128 MB
__device__ unsigned g_bpack[4194304];     // 4 packed Wx matrices (fragment-major) 16 MB
__device__ uint4    g_hpack[65536];       // rec h ping-pong: 2 dirs x 2 par x 16384 uint4 (1 MB)

// grid-barrier state (self-cleaning count; monotonically rising flag)
__device__ unsigned g_barcnt[2];
__device__ unsigned g_barflag[2];

// ---------------- tf32 helpers ----------------------------------------------
__device__ __forceinline__ unsigned f2tf32(float f) {
    unsigned r;
    asm("cvt.rna.tf32.f32 %0, %1;" : "=r"(r) : "f"(f));
    return r;
}

__device__ __forceinline__ void mma_tf32(float* c, const unsigned* a, const unsigned* b) {
    asm volatile(
        "mma.sync.aligned.m16n8k8.row.col.f32.tf32.tf32.f32 "
        "{%0,%1,%2,%3}, {%4,%5,%6,%7}, {%8,%9}, {%0,%1,%2,%3};"
        : "+f"(c[0]), "+f"(c[1]), "+f"(c[2]), "+f"(c[3])
        : "r"(a[0]), "r"(a[1]), "r"(a[2]), "r"(a[3]),
          "r"(b[0]), "r"(b[1]));
}

// ---------------- release/acquire primitives ---------------------------------
__device__ __forceinline__ unsigned atom_add_release(unsigned* p, unsigned v) {
    unsigned old;
    asm volatile("atom.release.gpu.global.add.u32 %0, [%1], %2;"
                 : "=r"(old) : "l"(p), "r"(v) : "memory");
    return old;
}
__device__ __forceinline__ void st_release(unsigned* p, unsigned v) {
    asm volatile("st.release.gpu.global.u32 [%0], %1;" :: "l"(p), "r"(v) : "memory");
}
__device__ __forceinline__ unsigned ld_acquire(unsigned* p) {
    unsigned v;
    asm volatile("ld.acquire.gpu.global.u32 %0, [%1];" : "=r"(v) : "l"(p) : "memory");
    return v;
}

// ---------------- operand pack kernels (unchanged from R10) ------------------
__global__ __launch_bounds__(256)
void pack_a(const float* __restrict__ A, unsigned* __restrict__ Ag)
{
    const int k8  = blockIdx.x;
    const int rg  = blockIdx.y * 8 + (threadIdx.x >> 5);
    const int lane = threadIdx.x & 31;
    const int g = lane >> 2, tig = lane & 3;
    const size_t r0 = (size_t)(rg * 16 + g) * 512;
    const size_t r1 = r0 + 8 * 512;
    const int c0 = k8 * 8 + tig;
    uint4 u;
    u.x = f2tf32(A[r0 + c0]);
    u.y = f2tf32(A[r1 + c0]);
    u.z = f2tf32(A[r0 + c0 + 4]);
    u.w = f2tf32(A[r1 + c0 + 4]);
    *(uint4*)(Ag + ((size_t)k8 * 2048 + rg) * 128 + lane * 4) = u;
}

__global__ __launch_bounds__(256)
void pack_b(const float* __restrict__ Wx, unsigned* __restrict__ Bg)
{
    const int k8 = blockIdx.x;
    const int n8 = blockIdx.y * 8 + (threadIdx.x >> 5);
    const int ld = blockIdx.z;
    const int lane = threadIdx.x & 31;
    const int g = lane >> 2, tig = lane & 3;
    const float* W = Wx + (size_t)ld * 512 * 2048;
    const size_t col = (size_t)n8 * 8 + g;
    uint2 u;
    u.x = f2tf32(W[(size_t)(k8 * 8 + tig)     * 2048 + col]);
    u.y = f2tf32(W[(size_t)(k8 * 8 + tig + 4) * 2048 + col]);
    *(uint2*)(Bg + (((size_t)ld * 64 + k8) * 256 + n8) * 64 + lane * 2) = u;
}

// ---------------- zero-smem packed-fragment GEMM (unchanged from R10) --------
__global__ __launch_bounds__(256)
void gemm_pk(const unsigned* __restrict__ Ag,
             const unsigned* __restrict__ Bg,
             const float* __restrict__ bias,
             float* __restrict__ C)
{
    const int tid  = threadIdx.x;
    const int wid  = tid >> 5;
    const int lane = tid & 31;
    const int g    = lane >> 2;
    const int tig  = lane & 3;
    const int wm   = wid >> 2;
    const int wn   = wid & 3;
    const long m0  = (long)blockIdx.y * 128;
    const int  n0  = blockIdx.x * 128;
    const int  rgb = blockIdx.y * 8 + wm * 4;
    const int  n8b = blockIdx.x * 16 + wn * 4;

    const uint4* __restrict__ A4 = (const uint4*)Ag;
    const uint2* __restrict__ B2 = (const uint2*)Bg;

    float acc[4][4][4];
#pragma unroll
    for (int i = 0; i < 4; i++)
#pragma unroll
        for (int j = 0; j < 4; j++)
#pragma unroll
            for (int q = 0; q < 4; q++) acc[i][j][q] = 0.f;

    uint4 av[4]; uint2 bv[4];
#pragma unroll
    for (int mt = 0; mt < 4; mt++)
        av[mt] = A4[(size_t)(rgb + mt) * 32 + lane];
#pragma unroll
    for (int nt = 0; nt < 4; nt++)
        bv[nt] = B2[(size_t)(n8b + nt) * 32 + lane];

#pragma unroll 4
    for (int k8 = 0; k8 < 64; k8++) {
        uint4 an[4]; uint2 bn[4];
        if (k8 < 63) {
            const size_t ao = (size_t)(k8 + 1) * 65536;
            const size_t bo = (size_t)(k8 + 1) * 8192;
#pragma unroll
            for (int mt = 0; mt < 4; mt++)
                an[mt] = A4[ao + (size_t)(rgb + mt) * 32 + lane];
#pragma unroll
            for (int nt = 0; nt < 4; nt++)
                bn[nt] = B2[bo + (size_t)(n8b + nt) * 32 + lane];
        }
#pragma unroll
        for (int mt = 0; mt < 4; mt++)
#pragma unroll
            for (int nt = 0; nt < 4; nt++)
                mma_tf32(acc[mt][nt], (const unsigned*)&av[mt],
                         (const unsigned*)&bv[nt]);
        if (k8 < 63) {
#pragma unroll
            for (int mt = 0; mt < 4; mt++) av[mt] = an[mt];
#pragma unroll
            for (int nt = 0; nt < 4; nt++) bv[nt] = bn[nt];
        }
    }

#pragma unroll
    for (int mt = 0; mt < 4; mt++) {
#pragma unroll
        for (int nt = 0; nt < 4; nt++) {
            long r0 = m0 + wm * 64 + mt * 16 + g;
            int cc = n0 + wn * 32 + nt * 8 + tig * 2;
            float b0 = bias[cc], b1 = bias[cc + 1];
            C[r0 * 2048 + cc]           = acc[mt][nt][0] + b0;
            C[r0 * 2048 + cc + 1]       = acc[mt][nt][1] + b1;
            C[(r0 + 8) * 2048 + cc]     = acc[mt][nt][2] + b0;
            C[(r0 + 8) * 2048 + cc + 1] = acc[mt][nt][3] + b1;
        }
    }
}

// ---------------- recurrence: fragment-major h ping-pong, no split-K ----------
// grid (32 j-tiles, 2 M-halves, 2 dirs) = 128 CTAs, 512 threads.
// CTA: M = 64 batches (mh*64), j range 16 (q*16). Warps: wm(4 M-groups) x wjq(4).
// Thread owns (r0, r0+8) x ONE j with all 4 gates in registers (gate-interleaved
// B packing). A operand = packed tf32 h from previous step: 1 LDG.128/warp/k8.
struct RecP {
    const float* xp[2];   // per dir input projections [B*T, 2048]
    const float* Wh[2];   // per dir [512, 2048]
    float*       h[2];    // per dir fp32 h base
    long bstride;
    long tstride;
};

#define REC_SMEM (64 * 4 * 128 * 4)   // Bp: [k8][wjq][lane*4 + gp*2 + e] = 128 KB

__global__ __launch_bounds__(512)
void lstm_rec(RecP p)
{
    extern __shared__ unsigned Bp[];

    const int q    = blockIdx.x;        // j-tile: j in [q*16, q*16+16)
    const int mh   = blockIdx.y;        // M half: rows [mh*64, mh*64+64)
    const int dir  = blockIdx.z;
    const int tid  = threadIdx.x;
    const int wid  = tid >> 5;
    const int lane = tid & 31;
    const int g    = lane >> 2;
    const int tig  = lane & 3;
    const int wm   = wid & 3;           // M-group within half
    const int wjq  = wid >> 2;          // j-quad 0..3

    const float* __restrict__ xp = p.xp[dir];
    const float* __restrict__ Wh = p.Wh[dir];
    float* __restrict__ hb = p.h[dir];
    const long bstride = p.bstride;
    const long tstride = p.tstride;

    // ---- pack Wh gate-interleaved fragments into smem (one-time) ----
    // frag (k8, wj, gp): n-index nn = lane>>2 -> gate = gp*2 + (nn&1),
    //                    jloc = nn>>1; rows k8*8+tig (+4).
#pragma unroll
    for (int i = 0; i < 4; i++) {
        const int k8 = wid * 4 + i;
#pragma unroll
        for (int wj = 0; wj < 4; wj++) {
#pragma unroll
            for (int gp = 0; gp < 2; gp++) {
                const int nn = g;
                const size_t col = (size_t)(gp * 2 + (nn & 1)) * 512
                                 + q * 16 + wj * 4 + (nn >> 1);
                unsigned v0 = f2tf32(Wh[(size_t)(k8 * 8 + tig)     * 2048 + col]);
                unsigned v1 = f2tf32(Wh[(size_t)(k8 * 8 + tig + 4) * 2048 + col]);
                Bp[(k8 * 4 + wj) * 128 + lane * 4 + gp * 2]     = v0;
                Bp[(k8 * 4 + wj) * 128 + lane * 4 + gp * 2 + 1] = v1;
            }
        }
    }
    __syncthreads();

    const int r0 = mh * 64 + wm * 16 + g;       // batch rows r0, r0+8
    const int j  = q * 16 + wjq * 4 + tig;      // this thread's hidden unit
    const int rg = mh * 4 + wm;                  // packed-h rowgroup (r0>>4)

    // packed-h bases (uint4 units): per dir 32768, per parity 16384
    uint4* hp_base = g_hpack + (size_t)dir * 32768;
    // packed write address pieces (step-invariant)
    const int k8p  = j >> 3;
    const int kbit = (j >> 2) & 1;
    const size_t woff = ((size_t)(k8p * 8 + rg)) * 128 + lane * 4 + kbit * 2;

    float creg[2] = {0.f, 0.f};

    for (int s = 0; s < TT; s++) {
        const int t = dir ? (TT - 1 - s) : s;

        // ---- prefetch xproj gates (consumed in epilogue; hidden under mma) ----
        float xv[4][2];
#pragma unroll
        for (int rr = 0; rr < 2; rr++) {
            const size_t xb = ((size_t)(r0 + rr * 8) * TT + t) * 2048 + j;
#pragma unroll
            for (int gt = 0; gt < 4; gt++)
                xv[gt][rr] = xp[xb + gt * 512];
        }

        float acc0[4] = {0.f, 0.f, 0.f, 0.f};   // gates i,f
        float acc1[4] = {0.f, 0.f, 0.f, 0.f};   // gates g,o

        if (s > 0) {
            const uint4* __restrict__ Ap =
                hp_base + (size_t)((s + 1) & 1) * 16384 + rg * 32 + lane;

            uint4 abuf[4];
#pragma unroll
            for (int i = 0; i < 4; i++) abuf[i] = Ap[i * 256];

#pragma unroll 4
            for (int k8 = 0; k8 < 64; k8++) {
                uint4 av = abuf[k8 & 3];
                if (k8 < 60) abuf[k8 & 3] = Ap[(size_t)(k8 + 4) * 256];
                uint4 bv = *(const uint4*)&Bp[(k8 * 4 + wjq) * 128 + lane * 4];
                mma_tf32(acc0, (const unsigned*)&av, (const unsigned*)&bv.x);
                mma_tf32(acc1, (const unsigned*)&av, (const unsigned*)&bv.z);
            }
        }

        // ---- activations + cell update (all 4 gates local) ----
        float hval[2];
#pragma unroll
        for (int rr = 0; rr < 2; rr++) {
            float gi = acc0[rr * 2]     + xv[0][rr];
            float gf = acc0[rr * 2 + 1] + xv[1][rr];
            float gg = acc1[rr * 2]     + xv[2][rr];
            float go = acc1[rr * 2 + 1] + xv[3][rr];
            float i_ = 1.f / (1.f + expf(-gi));
            float f_ = 1.f / (1.f + expf(-gf));
            float G_ = tanhf(gg);
            float o_ = 1.f / (1.f + expf(-go));
            float cn = f_ * creg[rr] + i_ * G_;
            creg[rr] = cn;
            hval[rr] = o_ * tanhf(cn);
        }

        // fp32 h (layer output / next-layer GEMM input)
#pragma unroll
        for (int rr = 0; rr < 2; rr++)
            hb[(size_t)(r0 + rr * 8) * bstride + (size_t)t * tstride + j] = hval[rr];

        // fragment-major tf32 h for next step's A operand
        {
            unsigned* wp = (unsigned*)(hp_base + (size_t)(s & 1) * 16384);
            wp[woff]     = f2tf32(hval[0]);
            wp[woff + 1] = f2tf32(hval[1]);
        }

        // ---- per-direction grid barrier (64 CTAs), skip after last step ----
        if (s < TT - 1) {
            __syncthreads();
            if (tid == 0) {
                unsigned oldf = ld_acquire(&g_barflag[dir]);
                unsigned v = atom_add_release(&g_barcnt[dir], 1);
                if (v == 63) {
                    g_barcnt[dir] = 0;
                    st_release(&g_barflag[dir], oldf + 1);
                } else {
                    while (ld_acquire(&g_barflag[dir]) == oldf) { }
                }
            }
            __syncthreads();
        }
    }
}

// ---------------- host orchestration ----------------------------------------
extern "C" void kernel_launch(void* const* d_in, const int* in_sizes, int n_in,
                              void* d_out, int out_size)
{
    const float* x  = (const float*)d_in[0];   // [128,256,512]
    const float* Wx = (const float*)d_in[1];   // [2,2,512,2048]
    const float* Wh = (const float*)d_in[2];   // [2,2,512,2048]
    const float* bs = (const float*)d_in[3];   // [2,2,2048]
    float* out = (float*)d_out;                // [128,256,1024]

    float *xp_base, *hist_base;
    unsigned *ap_base, *bp_base;
    cudaGetSymbolAddress((void**)&xp_base,   g_xproj);
    cudaGetSymbolAddress((void**)&hist_base, g_hist);
    cudaGetSymbolAddress((void**)&ap_base,   g_apack);
    cudaGetSymbolAddress((void**)&bp_base,   g_bpack);

    float* xp[2]   = { xp_base,   xp_base   + (size_t)BB * TT * G4 };
    float* hist[2] = { hist_base, hist_base + (size_t)BB * TT * HH };
    unsigned* ap[2] = { ap_base, ap_base + (size_t)64 * 2048 * 128 };

    const size_t WSTRIDE = (size_t)HH * G4;          // floats per (l,d) matrix
    const size_t BPSTRIDE = (size_t)64 * 256 * 64;   // words per packed B

    cudaFuncSetAttribute(lstm_rec, cudaFuncAttributeMaxDynamicSharedMemorySize,
                         REC_SMEM);

    const dim3 ggrid(16, 256);
    const dim3 agrid(64, 256);
    const dim3 rgrid(32, 2, 2);

    // ---- pack all 4 Wx matrices (one-shot, fragment-major) ----
    pack_b<<<dim3(64, 32, 4), 256>>>(Wx, bp_base);

    // ---- layer 0: pack x, run both direction projections ----
    pack_a<<<agrid, 256>>>(x, ap[0]);
    for (int d = 0; d < 2; d++)
        gemm_pk<<<ggrid, 256>>>(ap[0], bp_base + (size_t)d * BPSTRIDE,
                                bs + d * G4, xp[d]);

    // ---- layer 0 recurrence ----
    {
        RecP p;
        p.xp[0] = xp[0]; p.xp[1] = xp[1];
        p.Wh[0] = Wh;    p.Wh[1] = Wh + WSTRIDE;
        p.h[0]  = hist[0]; p.h[1] = hist[1];
        p.bstride = (long)TT * HH;
        p.tstride = HH;
        lstm_rec<<<rgrid, 512, REC_SMEM>>>(p);
    }

    // ---- layer 1: pack hidden histories, run projections ----
    pack_a<<<agrid, 256>>>(hist[0], ap[0]);
    pack_a<<<agrid, 256>>>(hist[1], ap[1]);
    for (int d = 0; d < 2; d++)
        gemm_pk<<<ggrid, 256>>>(ap[d], bp_base + (size_t)(2 + d) * BPSTRIDE,
                                bs + (2 + d) * G4, xp[d]);

    // ---- layer 1 recurrence (h lives directly in d_out) ----
    {
        RecP p;
        p.xp[0] = xp[0]; p.xp[1] = xp[1];
        p.Wh[0] = Wh + 2 * WSTRIDE; p.Wh[1] = Wh + 3 * WSTRIDE;
        p.h[0]  = out; p.h[1] = out + 512;
        p.bstride = (long)TT * 1024;
        p.tstride = 1024;
        lstm_rec<<<rgrid, 512, REC_SMEM>>>(p);
    }
}